// round 7
// baseline (speedup 1.0000x reference)
#include <cuda_runtime.h>
#include <cuda_bf16.h>

// ChamferLoss via exact pruned nearest-neighbor search.
// Morton counting-sort -> 32-point groups w/ bounding spheres -> per-warp
// distributed pruning: group needed iff dist(warp_center, grp_center) <=
// warp_max_ub + warp_radius + grp_radius (doubly-conservative triangle
// inequality -> exact mins). Final reduce fused into k_main (last block).

#define NPTS   16384
#define NBINS  4096           // 12-bit morton (4 bits/axis)
#define NGRP   (NPTS / 32)    // 512 groups per set
#define BT     128
#define NMAINBLK ((NPTS / BT) * 2)   // 256

#define INFF __int_as_float(0x7f800000)

__device__ float4       g_sorted[2][NPTS];   // {x,y,z, 0.5*|p|^2}
__device__ unsigned     g_code[2][NPTS];
__device__ unsigned     g_hist[2][NBINS];
__device__ unsigned     g_off[2][NBINS];
__device__ float4       g_bounds[2][NGRP];   // {cx,cy,cz, r}
__device__ float        g_dist[2][NPTS];     // per-point NN distance
__device__ unsigned     g_done;              // zero at load; self-resetting

// ---------- K0: zero histograms ----------
__global__ void k_zero() {
    int i = blockIdx.x * blockDim.x + threadIdx.x;
    if (i < 2 * NBINS) (&g_hist[0][0])[i] = 0;
}

__device__ __forceinline__ unsigned spread4(unsigned v) {
    return (v & 1u) | ((v & 2u) << 2) | ((v & 4u) << 4) | ((v & 8u) << 6);
}
__device__ __forceinline__ unsigned morton(float x, float y, float z) {
    int qx = (int)((x + 5.0f) * 1.6f); qx = max(0, min(15, qx));
    int qy = (int)((y + 5.0f) * 1.6f); qy = max(0, min(15, qy));
    int qz = (int)((z + 5.0f) * 1.6f); qz = max(0, min(15, qz));
    return spread4((unsigned)qx) | (spread4((unsigned)qy) << 1) | (spread4((unsigned)qz) << 2);
}

// ---------- K1: codes + histogram ----------
__global__ void k_code(const float* __restrict__ pred, const float* __restrict__ gt) {
    int i = blockIdx.x * blockDim.x + threadIdx.x;
    if (i >= 2 * NPTS) return;
    int s = i >> 14, p = i & (NPTS - 1);
    const float* src = s ? gt : pred;
    unsigned c = morton(src[3 * p], src[3 * p + 1], src[3 * p + 2]);
    g_code[s][p] = c;
    atomicAdd(&g_hist[s][c], 1u);
}

// ---------- K2: exclusive scan -> g_off (1 block, 4 bins/thread) ----------
__global__ __launch_bounds__(1024) void k_scan() {
    __shared__ unsigned part[1024];
    const int t = threadIdx.x;
    for (int s = 0; s < 2; ++s) {
        const int base = t * 4;
        unsigned h0 = g_hist[s][base + 0];
        unsigned h1 = g_hist[s][base + 1];
        unsigned h2 = g_hist[s][base + 2];
        unsigned h3 = g_hist[s][base + 3];
        part[t] = h0 + h1 + h2 + h3;
        __syncthreads();
        for (int d = 1; d < 1024; d <<= 1) {
            unsigned v = (t >= d) ? part[t - d] : 0u;
            __syncthreads();
            part[t] += v;
            __syncthreads();
        }
        unsigned excl = (t == 0) ? 0u : part[t - 1];
        g_off[s][base + 0] = excl;
        g_off[s][base + 1] = excl + h0;
        g_off[s][base + 2] = excl + h0 + h1;
        g_off[s][base + 3] = excl + h0 + h1 + h2;
        __syncthreads();
    }
}

// ---------- K3: scatter (bump g_off directly; rebuilt every replay) ----------
__global__ void k_scatter(const float* __restrict__ pred, const float* __restrict__ gt) {
    int i = blockIdx.x * blockDim.x + threadIdx.x;
    if (i >= 2 * NPTS) return;
    int s = i >> 14, p = i & (NPTS - 1);
    const float* src = s ? gt : pred;
    float x = src[3 * p], y = src[3 * p + 1], z = src[3 * p + 2];
    unsigned pos = atomicAdd(&g_off[s][g_code[s][p]], 1u);
    g_sorted[s][pos] = make_float4(x, y, z, 0.5f * (x * x + y * y + z * z));
}

// ---------- K4: group bounding spheres (1 warp per group) ----------
__global__ void k_bounds() {
    int gid = (blockIdx.x * blockDim.x + threadIdx.x) >> 5;
    int lane = threadIdx.x & 31;
    if (gid >= 2 * NGRP) return;
    int s = gid >= NGRP, g = gid & (NGRP - 1);
    float4 pv = g_sorted[s][g * 32 + lane];
    float sx = pv.x, sy = pv.y, sz = pv.z;
#pragma unroll
    for (int d = 16; d > 0; d >>= 1) {
        sx += __shfl_xor_sync(0xffffffffu, sx, d);
        sy += __shfl_xor_sync(0xffffffffu, sy, d);
        sz += __shfl_xor_sync(0xffffffffu, sz, d);
    }
    float cx = sx * (1.0f / 32.0f), cy = sy * (1.0f / 32.0f), cz = sz * (1.0f / 32.0f);
    float dx = pv.x - cx, dy = pv.y - cy, dz = pv.z - cz;
    float r2 = dx * dx + dy * dy + dz * dz;
#pragma unroll
    for (int d = 16; d > 0; d >>= 1)
        r2 = fmaxf(r2, __shfl_xor_sync(0xffffffffu, r2, d));
    if (lane == 0)
        g_bounds[s][g] = make_float4(cx, cy, cz, sqrtf(r2));
}

// ---------- K5: pruned sweep + fused final reduce ----------
__global__ __launch_bounds__(BT) void k_main(float* __restrict__ out) {
    const int dir = blockIdx.z;
    const int sx = dir, sy = dir ^ 1;

    __shared__ float4 sb[NGRP];
    __shared__ float4 stage[BT];
    __shared__ float  red[BT];
    __shared__ unsigned s_ticket;

    for (int i = threadIdx.x; i < NGRP; i += BT) sb[i] = g_bounds[sy][i];
    __syncthreads();

    const int p = blockIdx.x * BT + threadIdx.x;
    const float4 xp = g_sorted[sx][p];
    const float x2 = 2.0f * xp.w;
    const int lane = threadIdx.x & 31;
    const int wbase = threadIdx.x & ~31;
    const int g0 = (blockIdx.x * BT + wbase) >> 5;

    float ma = INFF, mb = INFF;   // two accumulators of min(0.5|y|^2 - x.y)

#define EVAL_GROUP(G)                                              \
    do {                                                           \
        stage[threadIdx.x] = g_sorted[sy][(G) * 32 + lane];        \
        __syncwarp();                                              \
        _Pragma("unroll")                                          \
        for (int i2 = 0; i2 < 32; i2 += 2) {                       \
            float4 ya = stage[wbase + i2];                         \
            float4 yb = stage[wbase + i2 + 1];                     \
            float ta = fmaf(-xp.x, ya.x, ya.w);                    \
            ta = fmaf(-xp.y, ya.y, ta);                            \
            ta = fmaf(-xp.z, ya.z, ta);                            \
            ma = fminf(ma, ta);                                    \
            float tb = fmaf(-xp.x, yb.x, yb.w);                    \
            tb = fmaf(-xp.y, yb.y, tb);                            \
            tb = fmaf(-xp.z, yb.z, tb);                            \
            mb = fminf(mb, tb);                                    \
        }                                                          \
        __syncwarp();                                              \
    } while (0)

    // Seed: evaluate own group +/- 1 unconditionally.
    const int s0 = max(g0 - 1, 0), s1 = min(g0 + 1, NGRP - 1);
    for (int g = s0; g <= s1; ++g) EVAL_GROUP(g);

    // Warp bounding sphere of the 32 x-points.
    float cx = xp.x, cy = xp.y, cz = xp.z;
#pragma unroll
    for (int d = 16; d > 0; d >>= 1) {
        cx += __shfl_xor_sync(0xffffffffu, cx, d);
        cy += __shfl_xor_sync(0xffffffffu, cy, d);
        cz += __shfl_xor_sync(0xffffffffu, cz, d);
    }
    cx *= (1.0f / 32.0f); cy *= (1.0f / 32.0f); cz *= (1.0f / 32.0f);
    float wx = xp.x - cx, wy = xp.y - cy, wz = xp.z - cz;
    float rw2 = wx * wx + wy * wy + wz * wz;
#pragma unroll
    for (int d = 16; d > 0; d >>= 1)
        rw2 = fmaxf(rw2, __shfl_xor_sync(0xffffffffu, rw2, d));
    const float rw = sqrtf(rw2);

    // Distributed check sweep: lane L checks group base+L; ballot; eval survivors.
    for (int base = 0; base < NGRP; base += 32) {
        // Tighten warp-max ub each batch.
        float ub = sqrtf(fmaxf(fmaf(2.0f, fminf(ma, mb), x2), 0.0f));
#pragma unroll
        for (int d = 16; d > 0; d >>= 1)
            ub = fmaxf(ub, __shfl_xor_sync(0xffffffffu, ub, d));
        const float lim = ub + rw;

        float4 b = sb[base + lane];
        float d0 = cx - b.x, d1 = cy - b.y, d2c = cz - b.z;
        float dc2 = fmaf(d0, d0, fmaf(d1, d1, d2c * d2c));
        float thr = lim + b.w;
        unsigned mask = __ballot_sync(0xffffffffu, dc2 <= thr * thr);
        while (mask) {
            int g = base + (__ffs(mask) - 1);
            mask &= mask - 1;
            if (g >= s0 && g <= s1) continue;   // seeds already evaluated
            EVAL_GROUP(g);
        }
    }

    // Per-point NN distance (exact; pruning is conservative).
    g_dist[dir][p] = sqrtf(fmaxf(fmaf(2.0f, fminf(ma, mb), x2), 0.0f));

    // Fused final reduce: last block to finish sums everything.
    __threadfence();
    __syncthreads();
    if (threadIdx.x == 0) s_ticket = atomicAdd(&g_done, 1u);
    __syncthreads();
    if (s_ticket == NMAINBLK - 1) {
        if (threadIdx.x == 0) g_done = 0;   // reset for next graph replay
        __threadfence();
        const float* dd = &g_dist[0][0];
        float s = 0.0f;
        for (int i = threadIdx.x; i < 2 * NPTS; i += BT) s += dd[i];
        red[threadIdx.x] = s;
        __syncthreads();
        for (int w = BT / 2; w > 0; w >>= 1) {
            if (threadIdx.x < w) red[threadIdx.x] += red[threadIdx.x + w];
            __syncthreads();
        }
        if (threadIdx.x == 0) out[0] = red[0] * (1.0f / (float)NPTS);
    }
}

extern "C" void kernel_launch(void* const* d_in, const int* in_sizes, int n_in,
                              void* d_out, int out_size) {
    const float* pred = (const float*)d_in[0];
    const float* gt   = (const float*)d_in[1];
    float* out = (float*)d_out;

    k_zero<<<(2 * NBINS + 255) / 256, 256>>>();
    k_code<<<(2 * NPTS + 255) / 256, 256>>>(pred, gt);
    k_scan<<<1, 1024>>>();
    k_scatter<<<(2 * NPTS + 255) / 256, 256>>>(pred, gt);
    k_bounds<<<(2 * NGRP * 32 + 255) / 256, 256>>>();
    dim3 grid(NPTS / BT, 1, 2);
    k_main<<<grid, BT>>>(out);
}

// round 8
// speedup vs baseline: 1.5952x; 1.5952x over previous
#include <cuda_runtime.h>
#include <cuda_bf16.h>

// ChamferLoss via exact pruned NN search.
// Morton counting-sort (32^3 grid, 15-bit) -> 32-pt groups + 8-group supergroups
// with AABBs -> per-point squared-distance box checks (no warp-sphere slack),
// warp-union via redux.or, warp-collective group evals. Pruning is conservative
// (a box containing the true NN always survives its owner's check) -> exact mins.

#define NPTS   16384
#define NBINS  32768          // 15-bit morton (5 bits/axis)
#define NGRP   (NPTS / 32)    // 512 groups per set
#define NSUP   (NGRP / 8)     // 64 supergroups per set
#define BT     128
#define NMAINBLK ((NPTS / BT) * 2)   // 256

#define INFF __int_as_float(0x7f800000)

__device__ float4   g_sorted[2][NPTS];      // {x,y,z, 0.5*|p|^2}
__device__ unsigned g_code[2][NPTS];
__device__ unsigned g_hist[2][NBINS];
__device__ unsigned g_off[2][NBINS];
__device__ float4   g_gaabb[2][NGRP][2];    // group AABB {min,xyz},{max,xyz}
__device__ float    g_dist[2][NPTS];
__device__ unsigned g_done;                 // zero-init; self-resetting

// ---------- K0: zero histograms ----------
__global__ void k_zero() {
    int i = blockIdx.x * blockDim.x + threadIdx.x;
    if (i < 2 * NBINS) (&g_hist[0][0])[i] = 0;
}

__device__ __forceinline__ unsigned spread5(unsigned v) {
    return (v & 1u) | ((v & 2u) << 2) | ((v & 4u) << 4) |
           ((v & 8u) << 6) | ((v & 16u) << 8);
}
__device__ __forceinline__ unsigned morton(float x, float y, float z) {
    int qx = (int)((x + 5.0f) * 3.2f); qx = max(0, min(31, qx));
    int qy = (int)((y + 5.0f) * 3.2f); qy = max(0, min(31, qy));
    int qz = (int)((z + 5.0f) * 3.2f); qz = max(0, min(31, qz));
    return spread5((unsigned)qx) | (spread5((unsigned)qy) << 1) | (spread5((unsigned)qz) << 2);
}

// ---------- K1: codes + histogram ----------
__global__ void k_code(const float* __restrict__ pred, const float* __restrict__ gt) {
    int i = blockIdx.x * blockDim.x + threadIdx.x;
    if (i >= 2 * NPTS) return;
    int s = i >> 14, p = i & (NPTS - 1);
    const float* src = s ? gt : pred;
    unsigned c = morton(src[3 * p], src[3 * p + 1], src[3 * p + 2]);
    g_code[s][p] = c;
    atomicAdd(&g_hist[s][c], 1u);
}

// ---------- K2: exclusive scan -> g_off (1 block, 32 bins/thread, reg-resident) ----------
__global__ __launch_bounds__(1024) void k_scan() {
    __shared__ unsigned part[1024];
    const int t = threadIdx.x;
    for (int s = 0; s < 2; ++s) {
        unsigned h[32];
        unsigned acc = 0;
#pragma unroll
        for (int k = 0; k < 32; ++k) { h[k] = g_hist[s][t * 32 + k]; acc += h[k]; }
        part[t] = acc;
        __syncthreads();
        for (int d = 1; d < 1024; d <<= 1) {
            unsigned v = (t >= d) ? part[t - d] : 0u;
            __syncthreads();
            part[t] += v;
            __syncthreads();
        }
        unsigned run = (t == 0) ? 0u : part[t - 1];
#pragma unroll
        for (int k = 0; k < 32; ++k) { g_off[s][t * 32 + k] = run; run += h[k]; }
        __syncthreads();
    }
}

// ---------- K3: scatter (bumps g_off; rebuilt every replay) ----------
__global__ void k_scatter(const float* __restrict__ pred, const float* __restrict__ gt) {
    int i = blockIdx.x * blockDim.x + threadIdx.x;
    if (i >= 2 * NPTS) return;
    int s = i >> 14, p = i & (NPTS - 1);
    const float* src = s ? gt : pred;
    float x = src[3 * p], y = src[3 * p + 1], z = src[3 * p + 2];
    unsigned pos = atomicAdd(&g_off[s][g_code[s][p]], 1u);
    g_sorted[s][pos] = make_float4(x, y, z, 0.5f * (x * x + y * y + z * z));
}

// ---------- K4: group AABBs (1 warp per group) ----------
__global__ void k_bounds() {
    int gid = (blockIdx.x * blockDim.x + threadIdx.x) >> 5;
    int lane = threadIdx.x & 31;
    if (gid >= 2 * NGRP) return;
    int s = gid >= NGRP, g = gid & (NGRP - 1);
    float4 pv = g_sorted[s][g * 32 + lane];
    float lx = pv.x, ly = pv.y, lz = pv.z;
    float hx = pv.x, hy = pv.y, hz = pv.z;
#pragma unroll
    for (int d = 16; d > 0; d >>= 1) {
        lx = fminf(lx, __shfl_xor_sync(0xffffffffu, lx, d));
        ly = fminf(ly, __shfl_xor_sync(0xffffffffu, ly, d));
        lz = fminf(lz, __shfl_xor_sync(0xffffffffu, lz, d));
        hx = fmaxf(hx, __shfl_xor_sync(0xffffffffu, hx, d));
        hy = fmaxf(hy, __shfl_xor_sync(0xffffffffu, hy, d));
        hz = fmaxf(hz, __shfl_xor_sync(0xffffffffu, hz, d));
    }
    if (lane == 0) {
        g_gaabb[s][g][0] = make_float4(lx, ly, lz, 0.0f);
        g_gaabb[s][g][1] = make_float4(hx, hy, hz, 0.0f);
    }
}

// dist^2 from point to AABB
__device__ __forceinline__ float boxd2(float px, float py, float pz,
                                       float4 lo, float4 hi) {
    float dx = fmaxf(fmaxf(lo.x - px, px - hi.x), 0.0f);
    float dy = fmaxf(fmaxf(lo.y - py, py - hi.y), 0.0f);
    float dz = fmaxf(fmaxf(lo.z - pz, pz - hi.z), 0.0f);
    return fmaf(dx, dx, fmaf(dy, dy, dz * dz));
}

// ---------- K5: pruned sweep + fused final reduce ----------
__global__ __launch_bounds__(BT) void k_main(float* __restrict__ out) {
    const int dir = blockIdx.z;
    const int sx = dir, sy = dir ^ 1;

    __shared__ float4 sb[NGRP][2];   // y group AABBs
    __shared__ float4 ssb[NSUP][2];  // y supergroup AABBs
    __shared__ float4 stage[BT];
    __shared__ float  red[BT];
    __shared__ unsigned s_ticket;

    for (int i = threadIdx.x; i < NGRP; i += BT) {
        sb[i][0] = g_gaabb[sy][i][0];
        sb[i][1] = g_gaabb[sy][i][1];
    }
    __syncthreads();
    if (threadIdx.x < NSUP) {
        float4 lo = sb[threadIdx.x * 8][0];
        float4 hi = sb[threadIdx.x * 8][1];
#pragma unroll
        for (int k = 1; k < 8; ++k) {
            float4 a = sb[threadIdx.x * 8 + k][0];
            float4 b = sb[threadIdx.x * 8 + k][1];
            lo.x = fminf(lo.x, a.x); lo.y = fminf(lo.y, a.y); lo.z = fminf(lo.z, a.z);
            hi.x = fmaxf(hi.x, b.x); hi.y = fmaxf(hi.y, b.y); hi.z = fmaxf(hi.z, b.z);
        }
        ssb[threadIdx.x][0] = lo;
        ssb[threadIdx.x][1] = hi;
    }
    __syncthreads();

    const int p = blockIdx.x * BT + threadIdx.x;
    const float4 xp = g_sorted[sx][p];
    const float x2 = 2.0f * xp.w;
    const int lane = threadIdx.x & 31;
    const int wbase = threadIdx.x & ~31;
    const int g0 = p >> 5;                       // warp-uniform
    const int s0 = max(g0 - 1, 0), s1 = min(g0 + 1, NGRP - 1);

    float ma = INFF, mb = INFF;

#define EVAL_GROUP(G)                                              \
    do {                                                           \
        stage[threadIdx.x] = g_sorted[sy][(G) * 32 + lane];        \
        __syncwarp();                                              \
        _Pragma("unroll")                                          \
        for (int i2 = 0; i2 < 32; i2 += 2) {                       \
            float4 ya = stage[wbase + i2];                         \
            float4 yb = stage[wbase + i2 + 1];                     \
            float ta = fmaf(-xp.x, ya.x, ya.w);                    \
            ta = fmaf(-xp.y, ya.y, ta);                            \
            ta = fmaf(-xp.z, ya.z, ta);                            \
            ma = fminf(ma, ta);                                    \
            float tb = fmaf(-xp.x, yb.x, yb.w);                    \
            tb = fmaf(-xp.y, yb.y, tb);                            \
            tb = fmaf(-xp.z, yb.z, tb);                            \
            mb = fminf(mb, tb);                                    \
        }                                                          \
        __syncwarp();                                              \
    } while (0)

    // Seed: own morton neighborhood (warp-uniform range).
    for (int g = s0; g <= s1; ++g) EVAL_GROUP(g);

    float d2ub = fmaxf(fmaf(2.0f, fminf(ma, mb), x2), 0.0f);

    // Phase 1: per-point supergroup checks, branch-free mask build.
    unsigned pm0 = 0, pm1 = 0;
#pragma unroll
    for (int i = 0; i < 32; ++i)
        if (boxd2(xp.x, xp.y, xp.z, ssb[i][0], ssb[i][1]) <= d2ub) pm0 |= 1u << i;
#pragma unroll
    for (int i = 0; i < 32; ++i)
        if (boxd2(xp.x, xp.y, xp.z, ssb[32 + i][0], ssb[32 + i][1]) <= d2ub) pm1 |= 1u << i;
    unsigned um0 = __reduce_or_sync(0xffffffffu, pm0);
    unsigned um1 = __reduce_or_sync(0xffffffffu, pm1);

    // Phase 2/3: expand surviving supergroups; per-point group checks; eval union.
    for (int half = 0; half < 2; ++half) {
        unsigned um = half ? um1 : um0;
        while (um) {
            int sgi = __ffs(um) - 1;
            um &= um - 1;
            int sg = half * 32 + sgi;
            d2ub = fmaxf(fmaf(2.0f, fminf(ma, mb), x2), 0.0f);   // re-tighten
            unsigned gm = 0;
#pragma unroll
            for (int b = 0; b < 8; ++b) {
                int g = sg * 8 + b;
                if (boxd2(xp.x, xp.y, xp.z, sb[g][0], sb[g][1]) <= d2ub) gm |= 1u << b;
            }
            gm = __reduce_or_sync(0xffffffffu, gm);
            while (gm) {
                int b = __ffs(gm) - 1;
                gm &= gm - 1;
                int g = sg * 8 + b;
                if (g >= s0 && g <= s1) continue;   // seeds already done
                EVAL_GROUP(g);
            }
        }
    }

    g_dist[dir][p] = sqrtf(fmaxf(fmaf(2.0f, fminf(ma, mb), x2), 0.0f));

    // Fused final reduce: last block sums everything.
    __threadfence();
    __syncthreads();
    if (threadIdx.x == 0) s_ticket = atomicAdd(&g_done, 1u);
    __syncthreads();
    if (s_ticket == NMAINBLK - 1) {
        if (threadIdx.x == 0) g_done = 0;   // reset for next graph replay
        __threadfence();
        const float* dd = &g_dist[0][0];
        float s = 0.0f;
        for (int i = threadIdx.x; i < 2 * NPTS; i += BT) s += dd[i];
        red[threadIdx.x] = s;
        __syncthreads();
        for (int w = BT / 2; w > 0; w >>= 1) {
            if (threadIdx.x < w) red[threadIdx.x] += red[threadIdx.x + w];
            __syncthreads();
        }
        if (threadIdx.x == 0) out[0] = red[0] * (1.0f / (float)NPTS);
    }
}

extern "C" void kernel_launch(void* const* d_in, const int* in_sizes, int n_in,
                              void* d_out, int out_size) {
    const float* pred = (const float*)d_in[0];
    const float* gt   = (const float*)d_in[1];
    float* out = (float*)d_out;

    k_zero<<<(2 * NBINS + 255) / 256, 256>>>();
    k_code<<<(2 * NPTS + 255) / 256, 256>>>(pred, gt);
    k_scan<<<1, 1024>>>();
    k_scatter<<<(2 * NPTS + 255) / 256, 256>>>(pred, gt);
    k_bounds<<<(2 * NGRP * 32 + 255) / 256, 256>>>();
    dim3 grid(NPTS / BT, 1, 2);
    k_main<<<grid, BT>>>(out);
}

// round 9
// speedup vs baseline: 1.6459x; 1.0318x over previous
#include <cuda_runtime.h>
#include <cuda_bf16.h>

// ChamferLoss via exact pruned NN search, straggler-free.
// Morton counting-sort (32^3) -> 32-pt groups + 8-group supergroup AABBs.
// k_boundseed: group AABBs + per-warp seed evals (morton neighbors) -> global ub.
// k_sweep: 8192 fine work units (dir, xgroup, ychunk-of-64-groups) via atomic
// work queue; per-point AABB checks vs global ub (conservative -> exact mins);
// warp-collective evals; atomicMin combine; fused final reduce.

#define NPTS   16384
#define NBINS  32768
#define NGRP   512            // 32-pt groups per set
#define NSUP   64             // 8-group supergroups per set
#define NCHUNK 8              // y-chunks per dir (8 supergroups each)
#define NUNITS (2 * NGRP * NCHUNK)   // 8192
#define SWEEPBLK 256

#define INFF __int_as_float(0x7f800000)

__device__ float4   g_sorted[2][NPTS];
__device__ unsigned g_code[2][NPTS];
__device__ unsigned g_hist[2][NBINS];
__device__ unsigned g_off[2][NBINS];
__device__ float4   g_gaabb[2][NGRP][2];
__device__ unsigned g_minbits[2 * NPTS];
__device__ unsigned g_work;
__device__ unsigned g_done;

// ---------- K0: zero histograms ----------
__global__ void k_zero() {
    int i = blockIdx.x * blockDim.x + threadIdx.x;
    if (i < 2 * NBINS) (&g_hist[0][0])[i] = 0;
}

__device__ __forceinline__ unsigned spread5(unsigned v) {
    return (v & 1u) | ((v & 2u) << 2) | ((v & 4u) << 4) |
           ((v & 8u) << 6) | ((v & 16u) << 8);
}
__device__ __forceinline__ unsigned morton(float x, float y, float z) {
    int qx = (int)((x + 5.0f) * 3.2f); qx = max(0, min(31, qx));
    int qy = (int)((y + 5.0f) * 3.2f); qy = max(0, min(31, qy));
    int qz = (int)((z + 5.0f) * 3.2f); qz = max(0, min(31, qz));
    return spread5((unsigned)qx) | (spread5((unsigned)qy) << 1) | (spread5((unsigned)qz) << 2);
}

// ---------- K1: codes + histogram ----------
__global__ void k_code(const float* __restrict__ pred, const float* __restrict__ gt) {
    int i = blockIdx.x * blockDim.x + threadIdx.x;
    if (i >= 2 * NPTS) return;
    int s = i >> 14, p = i & (NPTS - 1);
    const float* src = s ? gt : pred;
    unsigned c = morton(src[3 * p], src[3 * p + 1], src[3 * p + 2]);
    g_code[s][p] = c;
    atomicAdd(&g_hist[s][c], 1u);
}

// ---------- K2: scan -> g_off; also init minbits + reset counters ----------
__global__ __launch_bounds__(1024) void k_scan() {
    __shared__ unsigned part[1024];
    const int t = threadIdx.x;
    for (int i = t; i < 2 * NPTS; i += 1024) g_minbits[i] = 0x7f800000u;
    if (t == 0) { g_work = 0; g_done = 0; }
    for (int s = 0; s < 2; ++s) {
        unsigned h[32];
        unsigned acc = 0;
#pragma unroll
        for (int k = 0; k < 32; ++k) { h[k] = g_hist[s][t * 32 + k]; acc += h[k]; }
        part[t] = acc;
        __syncthreads();
        for (int d = 1; d < 1024; d <<= 1) {
            unsigned v = (t >= d) ? part[t - d] : 0u;
            __syncthreads();
            part[t] += v;
            __syncthreads();
        }
        unsigned run = (t == 0) ? 0u : part[t - 1];
#pragma unroll
        for (int k = 0; k < 32; ++k) { g_off[s][t * 32 + k] = run; run += h[k]; }
        __syncthreads();
    }
}

// ---------- K3: scatter ----------
__global__ void k_scatter(const float* __restrict__ pred, const float* __restrict__ gt) {
    int i = blockIdx.x * blockDim.x + threadIdx.x;
    if (i >= 2 * NPTS) return;
    int s = i >> 14, p = i & (NPTS - 1);
    const float* src = s ? gt : pred;
    float x = src[3 * p], y = src[3 * p + 1], z = src[3 * p + 2];
    unsigned pos = atomicAdd(&g_off[s][g_code[s][p]], 1u);
    g_sorted[s][pos] = make_float4(x, y, z, 0.5f * (x * x + y * y + z * z));
}

#define EVAL_GROUP(SY, G)                                          \
    do {                                                           \
        stage[threadIdx.x] = g_sorted[SY][(G) * 32 + lane];        \
        __syncwarp();                                              \
        _Pragma("unroll")                                          \
        for (int i2 = 0; i2 < 32; i2 += 2) {                       \
            float4 ya = stage[wbase + i2];                         \
            float4 yb = stage[wbase + i2 + 1];                     \
            float ta = fmaf(-xp.x, ya.x, ya.w);                    \
            ta = fmaf(-xp.y, ya.y, ta);                            \
            ta = fmaf(-xp.z, ya.z, ta);                            \
            ma = fminf(ma, ta);                                    \
            float tb = fmaf(-xp.x, yb.x, yb.w);                    \
            tb = fmaf(-xp.y, yb.y, tb);                            \
            tb = fmaf(-xp.z, yb.z, tb);                            \
            mb = fminf(mb, tb);                                    \
        }                                                          \
        __syncwarp();                                              \
    } while (0)

// ---------- K4: fused group-AABBs + seed evals ----------
__global__ __launch_bounds__(256) void k_boundseed() {
    __shared__ float4 stage[256];
    const int lane = threadIdx.x & 31;
    const int wbase = threadIdx.x & ~31;
    const int gwid = blockIdx.x * 8 + (threadIdx.x >> 5);  // 0..2047

    if (gwid < 2 * NGRP) {
        // ---- bounds: one warp per group ----
        int s = gwid >= NGRP, g = gwid & (NGRP - 1);
        float4 pv = g_sorted[s][g * 32 + lane];
        float lx = pv.x, ly = pv.y, lz = pv.z;
        float hx = pv.x, hy = pv.y, hz = pv.z;
#pragma unroll
        for (int d = 16; d > 0; d >>= 1) {
            lx = fminf(lx, __shfl_xor_sync(0xffffffffu, lx, d));
            ly = fminf(ly, __shfl_xor_sync(0xffffffffu, ly, d));
            lz = fminf(lz, __shfl_xor_sync(0xffffffffu, lz, d));
            hx = fmaxf(hx, __shfl_xor_sync(0xffffffffu, hx, d));
            hy = fmaxf(hy, __shfl_xor_sync(0xffffffffu, hy, d));
            hz = fmaxf(hz, __shfl_xor_sync(0xffffffffu, hz, d));
        }
        if (lane == 0) {
            g_gaabb[s][g][0] = make_float4(lx, ly, lz, 0.0f);
            g_gaabb[s][g][1] = make_float4(hx, hy, hz, 0.0f);
        }
    } else {
        // ---- seed: one warp per x-group, eval morton neighbors xg-1..xg+1 ----
        int id = gwid - 2 * NGRP;
        int dir = id >= NGRP, xg = id & (NGRP - 1);
        int sy = dir ^ 1;
        int p = xg * 32 + lane;
        float4 xp = g_sorted[dir][p];
        float x2 = 2.0f * xp.w;
        float ma = INFF, mb = INFF;
        int s0 = max(xg - 1, 0), s1 = min(xg + 1, NGRP - 1);
        for (int g = s0; g <= s1; ++g) EVAL_GROUP(sy, g);
        float d2 = fmaxf(fmaf(2.0f, fminf(ma, mb), x2), 0.0f);
        atomicMin(&g_minbits[dir * NPTS + p], __float_as_uint(d2));
    }
}

__device__ __forceinline__ float boxd2(float px, float py, float pz,
                                       float4 lo, float4 hi) {
    float dx = fmaxf(fmaxf(lo.x - px, px - hi.x), 0.0f);
    float dy = fmaxf(fmaxf(lo.y - py, py - hi.y), 0.0f);
    float dz = fmaxf(fmaxf(lo.z - pz, pz - hi.z), 0.0f);
    return fmaf(dx, dx, fmaf(dy, dy, dz * dz));
}

// ---------- K5: work-stealing pruned sweep + fused final reduce ----------
__global__ __launch_bounds__(256) void k_sweep(float* __restrict__ out) {
    __shared__ float4 sb[2][NGRP][2];
    __shared__ float4 ssb[2][NSUP][2];
    __shared__ float4 stage[256];
    __shared__ float  red[256];
    __shared__ unsigned s_ticket;

    for (int i = threadIdx.x; i < 2 * NGRP; i += 256) {
        int s = i >= NGRP, g = i & (NGRP - 1);
        sb[s][g][0] = g_gaabb[s][g][0];
        sb[s][g][1] = g_gaabb[s][g][1];
    }
    __syncthreads();
    if (threadIdx.x < 2 * NSUP) {
        int s = threadIdx.x >= NSUP, i = threadIdx.x & (NSUP - 1);
        float4 lo = sb[s][i * 8][0];
        float4 hi = sb[s][i * 8][1];
#pragma unroll
        for (int k = 1; k < 8; ++k) {
            float4 a = sb[s][i * 8 + k][0];
            float4 b = sb[s][i * 8 + k][1];
            lo.x = fminf(lo.x, a.x); lo.y = fminf(lo.y, a.y); lo.z = fminf(lo.z, a.z);
            hi.x = fmaxf(hi.x, b.x); hi.y = fmaxf(hi.y, b.y); hi.z = fmaxf(hi.z, b.z);
        }
        ssb[s][i][0] = lo;
        ssb[s][i][1] = hi;
    }
    __syncthreads();

    const int lane = threadIdx.x & 31;
    const int wbase = threadIdx.x & ~31;

    for (;;) {
        unsigned uid;
        if (lane == 0) uid = atomicAdd(&g_work, 1u);
        uid = __shfl_sync(0xffffffffu, uid, 0);
        if (uid >= NUNITS) break;

        const int dir = uid & 1;
        const int xg  = (uid >> 1) & (NGRP - 1);
        const int yc  = uid >> 10;          // 0..7
        const int sy  = dir ^ 1;

        const int p = xg * 32 + lane;
        const float4 xp = g_sorted[dir][p];
        const float x2 = 2.0f * xp.w;
        float ub2 = __uint_as_float(g_minbits[dir * NPTS + p]);  // seeded, tightening
        float ma = INFF, mb = INFF;

        unsigned sgm = 0;
#pragma unroll
        for (int i = 0; i < 8; ++i) {
            int sg = yc * 8 + i;
            if (boxd2(xp.x, xp.y, xp.z, ssb[sy][sg][0], ssb[sy][sg][1]) <= ub2)
                sgm |= 1u << i;
        }
        sgm = __reduce_or_sync(0xffffffffu, sgm);
        while (sgm) {
            int i = __ffs(sgm) - 1;
            sgm &= sgm - 1;
            int sg = yc * 8 + i;
            unsigned gm = 0;
#pragma unroll
            for (int b = 0; b < 8; ++b) {
                int g = sg * 8 + b;
                if (boxd2(xp.x, xp.y, xp.z, sb[sy][g][0], sb[sy][g][1]) <= ub2)
                    gm |= 1u << b;
            }
            gm = __reduce_or_sync(0xffffffffu, gm);
            while (gm) {
                int b = __ffs(gm) - 1;
                gm &= gm - 1;
                EVAL_GROUP(sy, sg * 8 + b);
                ub2 = fminf(ub2, fmaxf(fmaf(2.0f, fminf(ma, mb), x2), 0.0f));
            }
        }
        if (fminf(ma, mb) < INFF) {
            float d2 = fmaxf(fmaf(2.0f, fminf(ma, mb), x2), 0.0f);
            atomicMin(&g_minbits[dir * NPTS + p], __float_as_uint(d2));
        }
    }

    // Fused final reduce: last block to drain the queue sums everything.
    __threadfence();
    __syncthreads();
    if (threadIdx.x == 0) s_ticket = atomicAdd(&g_done, 1u);
    __syncthreads();
    if (s_ticket == gridDim.x * gridDim.y * gridDim.z - 1) {
        __threadfence();
        float s = 0.0f;
        for (int i = threadIdx.x; i < 2 * NPTS; i += 256)
            s += sqrtf(__uint_as_float(g_minbits[i]));
        red[threadIdx.x] = s;
        __syncthreads();
        for (int w = 128; w > 0; w >>= 1) {
            if (threadIdx.x < w) red[threadIdx.x] += red[threadIdx.x + w];
            __syncthreads();
        }
        if (threadIdx.x == 0) out[0] = red[0] * (1.0f / (float)NPTS);
    }
}

extern "C" void kernel_launch(void* const* d_in, const int* in_sizes, int n_in,
                              void* d_out, int out_size) {
    const float* pred = (const float*)d_in[0];
    const float* gt   = (const float*)d_in[1];
    float* out = (float*)d_out;

    k_zero<<<(2 * NBINS + 255) / 256, 256>>>();
    k_code<<<(2 * NPTS + 255) / 256, 256>>>(pred, gt);
    k_scan<<<1, 1024>>>();
    k_scatter<<<(2 * NPTS + 255) / 256, 256>>>(pred, gt);
    k_boundseed<<<256, 256>>>();
    k_sweep<<<SWEEPBLK, 256>>>(out);
}

// round 10
// speedup vs baseline: 2.8318x; 1.7204x over previous
#include <cuda_runtime.h>
#include <cuda_bf16.h>

// ChamferLoss: fully-fused persistent kernel (single launch).
// Phases separated by global spin barriers (148 blocks = 148 SMs, co-resident):
//  P0 zero hist / init minbits      P1 morton code + histogram
//  P2 block-local scan (128x512)    P2b chunk prefix + offsets
//  P3 scatter                       P4 group AABBs
//  P5 smem AABBs + seed evals       P6 work-queue pruned sweep
//  ticket -> last block: reduce + counter reset (graph-replay safe).
// Pruning: group evaluated iff point-to-AABB d2 <= current ub2 (conservative
// -> exact mins, deterministic result).

#define NPTS   16384
#define NBINS  32768          // per set (15-bit morton)
#define NGRP   512
#define NSUP   64
#define NUNITS 8192           // 2 dirs * 512 xgroups * 8 ychunks
#define NBLK   148
#define NTHR   1024

#define INFF __int_as_float(0x7f800000)

__device__ float4   g_sorted[2][NPTS];
__device__ unsigned g_hist[2 * NBINS];
__device__ unsigned g_offs[2 * NBINS];
__device__ unsigned g_part[128];
__device__ float4   g_gaabb[2][NGRP][2];
__device__ unsigned g_minbits[2][NPTS];
__device__ unsigned g_bar, g_work, g_done;   // static-zero; reset by ticket winner

__device__ __forceinline__ unsigned spread5(unsigned v) {
    return (v & 1u) | ((v & 2u) << 2) | ((v & 4u) << 4) |
           ((v & 8u) << 6) | ((v & 16u) << 8);
}
__device__ __forceinline__ unsigned morton(float x, float y, float z) {
    int qx = (int)((x + 5.0f) * 3.2f); qx = max(0, min(31, qx));
    int qy = (int)((y + 5.0f) * 3.2f); qy = max(0, min(31, qy));
    int qz = (int)((z + 5.0f) * 3.2f); qz = max(0, min(31, qz));
    return spread5((unsigned)qx) | (spread5((unsigned)qy) << 1) | (spread5((unsigned)qz) << 2);
}

__device__ __forceinline__ void gsync(unsigned target) {
    __syncthreads();
    if (threadIdx.x == 0) {
        __threadfence();
        atomicAdd(&g_bar, 1u);
        while (atomicAdd(&g_bar, 0u) < target) __nanosleep(64);
    }
    __syncthreads();
}

__device__ __forceinline__ float boxd2(float px, float py, float pz,
                                       float4 lo, float4 hi) {
    float dx = fmaxf(fmaxf(lo.x - px, px - hi.x), 0.0f);
    float dy = fmaxf(fmaxf(lo.y - py, py - hi.y), 0.0f);
    float dz = fmaxf(fmaxf(lo.z - pz, pz - hi.z), 0.0f);
    return fmaf(dx, dx, fmaf(dy, dy, dz * dz));
}

// Warp-collective eval of 32-pt y-group G vs each lane's xp; 16-slot staging.
#define EVAL_GROUP(SY, G)                                                     \
    do {                                                                      \
        _Pragma("unroll")                                                     \
        for (int rr = 0; rr < 2; ++rr) {                                      \
            if (lane < 16)                                                    \
                stage[wslot + lane] = __ldcg(&g_sorted[SY][(G) * 32 + rr * 16 + lane]); \
            __syncwarp();                                                     \
            _Pragma("unroll")                                                 \
            for (int i2 = 0; i2 < 16; i2 += 2) {                              \
                float4 ya = stage[wslot + i2];                                \
                float4 yb = stage[wslot + i2 + 1];                            \
                float ta = fmaf(-xp.x, ya.x, ya.w);                           \
                ta = fmaf(-xp.y, ya.y, ta);                                   \
                ta = fmaf(-xp.z, ya.z, ta);                                   \
                ma = fminf(ma, ta);                                           \
                float tb = fmaf(-xp.x, yb.x, yb.w);                           \
                tb = fmaf(-xp.y, yb.y, tb);                                   \
                tb = fmaf(-xp.z, yb.z, tb);                                   \
                mb = fminf(mb, tb);                                           \
            }                                                                 \
            __syncwarp();                                                     \
        }                                                                     \
    } while (0)

__global__ __launch_bounds__(NTHR, 1) void k_all(const float* __restrict__ pred,
                                                 const float* __restrict__ gt,
                                                 float* __restrict__ out) {
    __shared__ float4 sb[2][NGRP][2];      // 32 KB group AABBs
    __shared__ float4 ssb[2][NSUP][2];     // 4 KB supergroup AABBs
    __shared__ __align__(16) unsigned char scratch[8192];  // stage | sscan | red
    __shared__ unsigned s_ticket;
    float4*   stage = (float4*)scratch;    // 512 slots (16 per warp)
    unsigned* sscan = (unsigned*)scratch;
    float*    red   = (float*)scratch;

    const int tid   = threadIdx.x;
    const int bid   = blockIdx.x;
    const int gi    = bid * NTHR + tid;
    const int lane  = tid & 31;
    const int wid   = tid >> 5;
    const int wslot = wid * 16;
    const int gw    = bid * (NTHR / 32) + wid;

    // ---- P0: zero hist, init minbits ----
    if (gi < 2 * NBINS) g_hist[gi] = 0;
    if (gi < 2 * NPTS) (&g_minbits[0][0])[gi] = 0x7f800000u;
    gsync(1 * NBLK);

    // ---- P1: code + histogram (item held in registers through P3) ----
    int my_s = -1;
    unsigned my_c = 0;
    float mx = 0.f, myy = 0.f, mz = 0.f;
    if (gi < 2 * NPTS) {
        my_s = gi >> 14;
        int p = gi & (NPTS - 1);
        const float* src = my_s ? gt : pred;
        mx = src[3 * p]; myy = src[3 * p + 1]; mz = src[3 * p + 2];
        my_c = morton(mx, myy, mz);
        atomicAdd(&g_hist[my_s * NBINS + my_c], 1u);
    }
    gsync(2 * NBLK);

    // ---- P2: block-local exclusive scan of this block's 512-bin chunk ----
    unsigned lexcl = 0;
    if (bid < 128) {
        unsigned h = (tid < 512) ? __ldcg(&g_hist[bid * 512 + tid]) : 0u;
        if (tid < 512) sscan[tid] = h;
        __syncthreads();
        for (int d = 1; d < 512; d <<= 1) {
            unsigned v = (tid >= d && tid < 512) ? sscan[tid - d] : 0u;
            __syncthreads();
            if (tid < 512) sscan[tid] += v;
            __syncthreads();
        }
        if (tid < 512) lexcl = sscan[tid] - h;
        if (tid == 511) g_part[bid] = sscan[511];
    }
    gsync(3 * NBLK);

    // ---- P2b: chunk prefixes + write offsets (set1 adjusted by -NPTS) ----
    if (bid < 128) {
        if (tid < 128) sscan[tid] = __ldcg(&g_part[tid]);
        __syncthreads();
        for (int d = 1; d < 128; d <<= 1) {
            unsigned v = (tid >= d && tid < 128) ? sscan[tid - d] : 0u;
            __syncthreads();
            if (tid < 128) sscan[tid] += v;
            __syncthreads();
        }
        unsigned prefix = (bid == 0) ? 0u : sscan[bid - 1];
        unsigned adj = (bid >= 64) ? (unsigned)NPTS : 0u;   // S[32768] == 16384
        if (tid < 512) g_offs[bid * 512 + tid] = lexcl + prefix - adj;
    }
    gsync(4 * NBLK);

    // ---- P3: scatter ----
    if (my_s >= 0) {
        unsigned pos = atomicAdd(&g_offs[my_s * NBINS + my_c], 1u);
        g_sorted[my_s][pos] =
            make_float4(mx, myy, mz, 0.5f * (mx * mx + myy * myy + mz * mz));
    }
    gsync(5 * NBLK);

    // ---- P4: group AABBs (one warp per group) ----
    if (gw < 2 * NGRP) {
        int s = gw >= NGRP, g = gw & (NGRP - 1);
        float4 pv = __ldcg(&g_sorted[s][g * 32 + lane]);
        float lx = pv.x, ly = pv.y, lz = pv.z;
        float hx = pv.x, hy = pv.y, hz = pv.z;
#pragma unroll
        for (int d = 16; d > 0; d >>= 1) {
            lx = fminf(lx, __shfl_xor_sync(0xffffffffu, lx, d));
            ly = fminf(ly, __shfl_xor_sync(0xffffffffu, ly, d));
            lz = fminf(lz, __shfl_xor_sync(0xffffffffu, lz, d));
            hx = fmaxf(hx, __shfl_xor_sync(0xffffffffu, hx, d));
            hy = fmaxf(hy, __shfl_xor_sync(0xffffffffu, hy, d));
            hz = fmaxf(hz, __shfl_xor_sync(0xffffffffu, hz, d));
        }
        if (lane == 0) {
            g_gaabb[s][g][0] = make_float4(lx, ly, lz, 0.0f);
            g_gaabb[s][g][1] = make_float4(hx, hy, hz, 0.0f);
        }
    }
    gsync(6 * NBLK);

    // ---- P5: AABBs into smem; seed evals (morton-neighbor groups) ----
    for (int i = tid; i < 2 * NGRP; i += NTHR) {
        int s = i >= NGRP, g = i & (NGRP - 1);
        sb[s][g][0] = __ldcg(&g_gaabb[s][g][0]);
        sb[s][g][1] = __ldcg(&g_gaabb[s][g][1]);
    }
    __syncthreads();
    if (tid < 2 * NSUP) {
        int s = tid >= NSUP, i = tid & (NSUP - 1);
        float4 lo = sb[s][i * 8][0];
        float4 hi = sb[s][i * 8][1];
#pragma unroll
        for (int k = 1; k < 8; ++k) {
            float4 a = sb[s][i * 8 + k][0];
            float4 b = sb[s][i * 8 + k][1];
            lo.x = fminf(lo.x, a.x); lo.y = fminf(lo.y, a.y); lo.z = fminf(lo.z, a.z);
            hi.x = fmaxf(hi.x, b.x); hi.y = fmaxf(hi.y, b.y); hi.z = fmaxf(hi.z, b.z);
        }
        ssb[s][i][0] = lo;
        ssb[s][i][1] = hi;
    }
    if (gw < 2 * NGRP) {
        int dir = gw >= NGRP, xg = gw & (NGRP - 1);
        int sy = dir ^ 1;
        float4 xp = __ldcg(&g_sorted[dir][xg * 32 + lane]);
        float x2 = 2.0f * xp.w;
        float ma = INFF, mb = INFF;
        int s0 = max(xg - 1, 0), s1 = min(xg + 1, NGRP - 1);
        for (int g = s0; g <= s1; ++g) EVAL_GROUP(sy, g);
        float d2 = fmaxf(fmaf(2.0f, fminf(ma, mb), x2), 0.0f);
        atomicMin(&g_minbits[dir][xg * 32 + lane], __float_as_uint(d2));
    }
    gsync(7 * NBLK);

    // ---- P6: work-queue pruned sweep ----
    for (;;) {
        unsigned u0;
        if (lane == 0) u0 = atomicAdd(&g_work, 2u);
        u0 = __shfl_sync(0xffffffffu, u0, 0);
        if (u0 >= NUNITS) break;
#pragma unroll 1
        for (int k = 0; k < 2; ++k) {
            unsigned uid = u0 + k;
            if (uid >= NUNITS) break;
            const int dir = uid & 1;
            const int xg  = (uid >> 1) & (NGRP - 1);
            const int yc  = uid >> 10;
            const int sy  = dir ^ 1;
            float4 xp = __ldcg(&g_sorted[dir][xg * 32 + lane]);
            float x2 = 2.0f * xp.w;
            float ub2 = __uint_as_float(__ldcg(&g_minbits[dir][xg * 32 + lane]));
            float ma = INFF, mb = INFF;
            unsigned sgm = 0;
#pragma unroll
            for (int i = 0; i < 8; ++i) {
                int sg = yc * 8 + i;
                if (boxd2(xp.x, xp.y, xp.z, ssb[sy][sg][0], ssb[sy][sg][1]) <= ub2)
                    sgm |= 1u << i;
            }
            sgm = __reduce_or_sync(0xffffffffu, sgm);
            while (sgm) {
                int i = __ffs(sgm) - 1;
                sgm &= sgm - 1;
                int sg = yc * 8 + i;
                unsigned gm = 0;
#pragma unroll
                for (int b = 0; b < 8; ++b) {
                    int g = sg * 8 + b;
                    if (boxd2(xp.x, xp.y, xp.z, sb[sy][g][0], sb[sy][g][1]) <= ub2)
                        gm |= 1u << b;
                }
                gm = __reduce_or_sync(0xffffffffu, gm);
                while (gm) {
                    int b = __ffs(gm) - 1;
                    gm &= gm - 1;
                    EVAL_GROUP(sy, sg * 8 + b);
                    ub2 = fminf(ub2, fmaxf(fmaf(2.0f, fminf(ma, mb), x2), 0.0f));
                }
            }
            if (fminf(ma, mb) < INFF) {
                float d2 = fmaxf(fmaf(2.0f, fminf(ma, mb), x2), 0.0f);
                atomicMin(&g_minbits[dir][xg * 32 + lane], __float_as_uint(d2));
            }
        }
    }

    // ---- ticket: last block reduces + resets counters ----
    __threadfence();
    __syncthreads();
    if (tid == 0) s_ticket = atomicAdd(&g_done, 1u);
    __syncthreads();
    if (s_ticket == NBLK - 1) {
        if (tid == 0) { g_bar = 0; g_work = 0; g_done = 0; }  // replay-safe
        __threadfence();
        float s = 0.0f;
        const unsigned* mb32 = &g_minbits[0][0];
        for (int i = tid; i < 2 * NPTS; i += NTHR)
            s += sqrtf(__uint_as_float(__ldcg(&mb32[i])));
        red[tid] = s;
        __syncthreads();
        for (int w = NTHR / 2; w > 0; w >>= 1) {
            if (tid < w) red[tid] += red[tid + w];
            __syncthreads();
        }
        if (tid == 0) out[0] = red[0] * (1.0f / (float)NPTS);
    }
}

extern "C" void kernel_launch(void* const* d_in, const int* in_sizes, int n_in,
                              void* d_out, int out_size) {
    const float* pred = (const float*)d_in[0];
    const float* gt   = (const float*)d_in[1];
    float* out = (float*)d_out;
    k_all<<<NBLK, NTHR>>>(pred, gt, out);
}